// round 14
// baseline (speedup 1.0000x reference)
#include <cuda_runtime.h>
#include <cuda_bf16.h>
#include <cstdint>
#include <math.h>

#define BB 4
#define CC 32
#define PP 262144
#define NI 8
#define EE 512
#define NPTS 4096
#define NPAIRS 28

#define NCHUNK_SEL 32
#define CHPX_SEL (PP / NCHUNK_SEL)     // 8192
#define SEL_BLKS (BB * NCHUNK_SEL)     // 128 (< 148 SMs: all wave-1 resident)
#define STATS_BLKS (BB * 128)          // 512 blocks x 512 threads x 2048 px
#define GATH_BLKS 256
#define VAR_BLKS 1024
#define KC_BLKS (GATH_BLKS + VAR_BLKS)
#define PAIR_BLKS (BB * NPAIRS * 8)    // 896

// ---------------- device scratch (static globals; no allocations) -------------
__device__ float g_sums[BB][NI][CC];
__device__ float g_counts[BB][NI];
__device__ int   g_cnt[BB][NCHUNK_SEL][NI];
__device__ int   g_sel[BB][NI][EE];
__device__ __align__(16) __nv_bfloat16 g_ebh[BB][NPTS][CC];
__device__ float g_sq[BB][NPTS];
__device__ float g_var_part[VAR_BLKS];
__device__ float g_edge_part[PAIR_BLKS];
__device__ int   g_selbar;   // sel-phase barrier (reset by kD finalize)
__device__ int   g_ticket;   // kD finalize ticket (reset by kD finalize)

// ====== kSelW: count + grid barrier + ranked write (128 blocks, 1 launch) =====
__global__ __launch_bounds__(256) void kSelW(const int* __restrict__ labelEdges) {
    int t = threadIdx.x;
    int lane = t & 31, wid = t >> 5;
    int b = blockIdx.x >> 5;
    int chunk = blockIdx.x & 31;
    const int* le = labelEdges + (size_t)b * PP + chunk * CHPX_SEL;
    int start = t * 32;

    // -------- phase 1: count own chunk per instance ---------------------------
    int cnt[NI];
#pragma unroll
    for (int n = 0; n < NI; n++) cnt[n] = 0;
#pragma unroll
    for (int k = 0; k < 8; k++) {
        int4 q = *(const int4*)&le[start + k * 4];
#pragma unroll
        for (int n = 0; n < NI; n++)
            cnt[n] += (q.x == n) + (q.y == n) + (q.z == n) + (q.w == n);
    }

    // warp inclusive scans + cross-warp prefixes (reused for phase 2)
    __shared__ int wtot[8][NI];
    int inc[NI];
#pragma unroll
    for (int n = 0; n < NI; n++) {
        int v = cnt[n];
#pragma unroll
        for (int off = 1; off < 32; off <<= 1) {
            int u = __shfl_up_sync(0xffffffffu, v, off);
            if (lane >= off) v += u;
        }
        inc[n] = v;
        if (lane == 31) wtot[wid][n] = v;
    }
    __syncthreads();
    __shared__ int wpre[8][NI];
    if (t < 64) {
        int w2 = t >> 3, n = t & 7;
        int s = 0;
        for (int w = 0; w < w2; w++) s += wtot[w][n];
        wpre[w2][n] = s;
    }
    __syncthreads();
    if (t < NI) g_cnt[b][chunk][t] = wpre[7][t] + wtot[7][t];

    // -------- grid barrier (all 128 blocks are resident) ----------------------
    __threadfence();
    __syncthreads();
    if (t == 0) {
        atomicAdd(&g_selbar, 1);
        volatile int* vp = &g_selbar;
        while (*vp < SEL_BLKS) __nanosleep(32);
    }
    __syncthreads();
    __threadfence();

    // -------- phase 2: ranked write -------------------------------------------
    __shared__ int spre[NI];
    if (t < NI) {
        int s = 0;
        for (int c = 0; c < chunk; c++) s += g_cnt[b][c][t];
        spre[t] = s;
    }
    __syncthreads();
    bool any = false;
#pragma unroll
    for (int n = 0; n < NI; n++) any |= (spre[n] < EE);
    if (!any) return;

    int rank[NI];
#pragma unroll
    for (int n = 0; n < NI; n++)
        rank[n] = spre[n] + wpre[wid][n] + inc[n] - cnt[n];

#pragma unroll
    for (int k = 0; k < 8; k++) {
        int4 q = *(const int4*)&le[start + k * 4];
        int p = chunk * CHPX_SEL + start + k * 4;
        int l0 = q.x, l1 = q.y, l2 = q.z, l3 = q.w;
        if (rank[l0] < EE) g_sel[b][l0][rank[l0]] = p;     rank[l0]++;
        if (rank[l1] < EE) g_sel[b][l1][rank[l1]] = p + 1; rank[l1]++;
        if (rank[l2] < EE) g_sel[b][l2][rank[l2]] = p + 2; rank[l2]++;
        if (rank[l3] < EE) g_sel[b][l3][rank[l3]] = p + 3; rank[l3]++;
    }
}

// ========== kStats: label sums + counts (512 thr, 2 ch/warp, low regs) ========
__global__ __launch_bounds__(512, 2) void kStats(const float* __restrict__ feat,
                                                 const int* __restrict__ labels) {
    int b = blockIdx.x >> 7;
    int chunk = blockIdx.x & 127;
    int base = chunk * 2048;
    const float* f = feat + (size_t)b * CC * PP;
    const int* lb = labels + (size_t)b * PP;
    int t = threadIdx.x;
    int lane = t & 31, wid = t >> 5;   // 16 warps

    __shared__ int slab[2048];
    *(int4*)&slab[t * 4] = *(const int4*)&lb[base + t * 4];
    __syncthreads();

    int c0 = wid * 2;                  // warp owns channels c0, c0+1
    float acc[NI][2];
#pragma unroll
    for (int n = 0; n < NI; n++) { acc[n][0] = 0.0f; acc[n][1] = 0.0f; }

#pragma unroll
    for (int it = 0; it < 16; it++) {
        int pofs = it * 128 + lane * 4;
        const float* fp = f + base + pofs;
        float4 va = *(const float4*)&fp[(size_t)(c0 + 0) * PP];
        float4 vb = *(const float4*)&fp[(size_t)(c0 + 1) * PP];
        int l[4] = { slab[pofs], slab[pofs + 1], slab[pofs + 2], slab[pofs + 3] };
        float vA[4] = { va.x, va.y, va.z, va.w };
        float vB[4] = { vb.x, vb.y, vb.z, vb.w };
#pragma unroll
        for (int j = 0; j < 4; j++) {
#pragma unroll
            for (int n = 0; n < NI; n++) {
                float m = (l[j] == n) ? 1.0f : 0.0f;
                acc[n][0] = fmaf(m, vA[j], acc[n][0]);
                acc[n][1] = fmaf(m, vB[j], acc[n][1]);
            }
        }
    }

#pragma unroll
    for (int n = 0; n < NI; n++)
#pragma unroll
        for (int e = 0; e < 2; e++) {
            float a = acc[n][e];
#pragma unroll
            for (int o = 16; o > 0; o >>= 1) a += __shfl_xor_sync(0xffffffffu, a, o);
            acc[n][e] = a;
        }
    if (lane == 0) {
#pragma unroll
        for (int n = 0; n < NI; n++) {
            atomicAdd(&g_sums[b][n][c0 + 0], acc[n][0]);
            atomicAdd(&g_sums[b][n][c0 + 1], acc[n][1]);
        }
    }

    if (wid == 0) {
        int cnt[NI];
#pragma unroll
        for (int n = 0; n < NI; n++) cnt[n] = 0;
        for (int i = lane; i < 2048; i += 32) {
            int l = slab[i];
#pragma unroll
            for (int n = 0; n < NI; n++) cnt[n] += (l == n);
        }
#pragma unroll
        for (int n = 0; n < NI; n++) {
            int a = cnt[n];
#pragma unroll
            for (int o = 16; o > 0; o >>= 1) a += __shfl_xor_sync(0xffffffffu, a, o);
            cnt[n] = a;
        }
        if (lane == 0) {
#pragma unroll
            for (int n = 0; n < NI; n++)
                atomicAdd(&g_counts[b][n], (float)cnt[n]);
        }
    }
}

// ====== kC: gather (256 blks) + var (1024), occupancy-forced to 6 CTA/SM ======
__global__ __launch_bounds__(256, 6) void kC(const float* __restrict__ feat,
                                             const int* __restrict__ labels) {
    int t = threadIdx.x;
    int lane = t & 31, wid = t >> 5;

    if (blockIdx.x < GATH_BLKS) {
        int gidx = blockIdx.x * 256 + t;
        int b = gidx >> 14;
        int r = gidx & 16383;
        int pt = r >> 2;
        int cg = r & 3;
        int inst = pt >> 9;
        int e = pt & (EE - 1);
        int idx = g_sel[b][inst][e];
        const float* f = feat + (size_t)b * CC * PP;

        float sq = 0.0f;
        unsigned pk[4];
#pragma unroll
        for (int k = 0; k < 4; k++) {
            float va = f[(size_t)(cg * 8 + 2 * k) * PP + idx];
            float vb = f[(size_t)(cg * 8 + 2 * k + 1) * PP + idx];
            sq += va * va + vb * vb;
            __nv_bfloat162 h = __floats2bfloat162_rn(va, vb);
            pk[k] = *reinterpret_cast<unsigned*>(&h);
        }
        *(uint4*)&g_ebh[b][pt][cg * 8] = make_uint4(pk[0], pk[1], pk[2], pk[3]);

        sq += __shfl_xor_sync(0xffffffffu, sq, 1);
        sq += __shfl_xor_sync(0xffffffffu, sq, 2);
        if (cg == 0) g_sq[b][pt] = sq;
        return;
    }

    int vb2 = blockIdx.x - GATH_BLKS;
    int b = vb2 >> 8;
    int chunk = vb2 & 255;
    int base = chunk * 1024;
    const float* f = feat + (size_t)b * CC * PP;
    const int* lb = labels + (size_t)b * PP;

    __shared__ float sm[NI * 36];
    __shared__ float sinv[NI];
    __shared__ float wred[8];
    {
        int n = wid, c = lane;
        float cntv = g_counts[b][n];
        sm[n * 36 + c] = g_sums[b][n][c] / cntv;
        if (c == 0) sinv[n] = 1.0f / cntv;
    }
    __syncthreads();

    int p4 = base + t * 4;
    int4 L = *(const int4*)&lb[p4];
    int lv[4] = { L.x, L.y, L.z, L.w };

    float d2[4] = { 0.0f, 0.0f, 0.0f, 0.0f };
#pragma unroll
    for (int cg = 0; cg < 8; cg++) {
        float4 v0 = *(const float4*)&f[(size_t)(cg * 4 + 0) * PP + p4];
        float4 v1 = *(const float4*)&f[(size_t)(cg * 4 + 1) * PP + p4];
        float4 v2 = *(const float4*)&f[(size_t)(cg * 4 + 2) * PP + p4];
        float4 v3 = *(const float4*)&f[(size_t)(cg * 4 + 3) * PP + p4];
        float vj[4][4] = { {v0.x, v1.x, v2.x, v3.x},
                           {v0.y, v1.y, v2.y, v3.y},
                           {v0.z, v1.z, v2.z, v3.z},
                           {v0.w, v1.w, v2.w, v3.w} };
#pragma unroll
        for (int j = 0; j < 4; j++) {
            float4 m = *(const float4*)&sm[lv[j] * 36 + cg * 4];
            float t0 = vj[j][0] - m.x;
            float t1 = vj[j][1] - m.y;
            float t2 = vj[j][2] - m.z;
            float t3 = vj[j][3] - m.w;
            d2[j] += t0 * t0 + t1 * t1 + t2 * t2 + t3 * t3;
        }
    }

    float hsum = 0.0f;
#pragma unroll
    for (int j = 0; j < 4; j++) {
        float d = sqrtf(d2[j] + 1e-12f);
        float h = fmaxf(d - 0.5f, 0.0f);          // DV = 0.5
        hsum += h * h * sinv[lv[j]];
    }
#pragma unroll
    for (int o = 16; o > 0; o >>= 1) hsum += __shfl_xor_sync(0xffffffffu, hsum, o);
    if (lane == 0) wred[wid] = hsum;
    __syncthreads();
    if (t == 0) {
        float s = 0.0f;
#pragma unroll
        for (int w2 = 0; w2 < 8; w2++) s += wred[w2];
        g_var_part[vb2] = s;
    }
}

// ========== kD: pairs (mma, 128x256, hoisted rare-path) + finalize ============
__global__ __launch_bounds__(256) void kD(float* __restrict__ out) {
    __shared__ __align__(16) __nv_bfloat16 As[128][40];
    __shared__ __align__(16) __nv_bfloat16 Bs[256][40];
    __shared__ float sqa[128];
    __shared__ __align__(8) float sqb[256];
    __shared__ float wred[8];
    __shared__ int s_last;

    int t = threadIdx.x;
    int lane = t & 31, wid = t >> 5;

    int id = blockIdx.x;
    int b = id / (NPAIRS * 8);
    int r2 = id % (NPAIRS * 8);
    int pair = r2 >> 3;
    int tile = r2 & 7;
    int i = 0, rem = pair;
    while (rem >= (NI - 1) - i) { rem -= (NI - 1) - i; i++; }
    int j = i + 1 + rem;
    int ti = tile >> 1, tj = tile & 1;
    int i0 = i * EE + ti * 128;
    int j0 = j * EE + tj * 256;

    {
        int row4 = t >> 2, ch8 = (t & 3) * 8;
#pragma unroll
        for (int rr = 0; rr < 2; rr++)
            *(uint4*)&As[row4 + rr * 64][ch8] =
                *(const uint4*)&g_ebh[b][i0 + row4 + rr * 64][ch8];
#pragma unroll
        for (int rr = 0; rr < 4; rr++)
            *(uint4*)&Bs[row4 + rr * 64][ch8] =
                *(const uint4*)&g_ebh[b][j0 + row4 + rr * 64][ch8];
    }
    if (t < 128) sqa[t] = g_sq[b][i0 + t];
    sqb[t] = g_sq[b][j0 + t];
    __syncthreads();

    int wi = wid >> 1, wj = wid & 1;
    int r0 = wi * 32, cb0 = wj * 128;
    int g = lane >> 2, tq = lane & 3;

    unsigned a[2][2][4];
#pragma unroll
    for (int rb = 0; rb < 2; rb++)
#pragma unroll
        for (int ks = 0; ks < 2; ks++) {
            int rbase = r0 + rb * 16;
            int kb = ks * 16 + 2 * tq;
            a[rb][ks][0] = *(const unsigned*)&As[rbase + g][kb];
            a[rb][ks][1] = *(const unsigned*)&As[rbase + g + 8][kb];
            a[rb][ks][2] = *(const unsigned*)&As[rbase + g][kb + 8];
            a[rb][ks][3] = *(const unsigned*)&As[rbase + g + 8][kb + 8];
        }
    float sa0[2] = { sqa[r0 + g],     sqa[r0 + 16 + g] };
    float sa1[2] = { sqa[r0 + 8 + g], sqa[r0 + 24 + g] };

    unsigned bs_u32 = (unsigned)__cvta_generic_to_shared(&Bs[0][0]);
    unsigned baddr = bs_u32 +
        (unsigned)(((cb0 + (lane & 7)) * 40 + (lane >> 3) * 8) * 2);

    float mn0 = 1e30f, mn1 = 1e30f, mn2 = 1e30f, mn3 = 1e30f;
#pragma unroll
    for (int nt = 0; nt < 16; nt++) {
        unsigned b00, b01, b10, b11;
        asm volatile(
            "ldmatrix.sync.aligned.m8n8.x4.shared.b16 {%0,%1,%2,%3}, [%4];"
            : "=r"(b00), "=r"(b01), "=r"(b10), "=r"(b11)
            : "r"(baddr + (unsigned)(nt * 8 * 80)));
        float2 sb = *(const float2*)&sqb[cb0 + nt * 8 + 2 * tq];
#pragma unroll
        for (int rb = 0; rb < 2; rb++) {
            float d0 = 0.0f, d1 = 0.0f, d2v = 0.0f, d3 = 0.0f;
            asm volatile(
                "mma.sync.aligned.m16n8k16.row.col.f32.bf16.bf16.f32 "
                "{%0,%1,%2,%3}, {%4,%5,%6,%7}, {%8,%9}, {%0,%1,%2,%3};"
                : "+f"(d0), "+f"(d1), "+f"(d2v), "+f"(d3)
                : "r"(a[rb][0][0]), "r"(a[rb][0][1]), "r"(a[rb][0][2]), "r"(a[rb][0][3]),
                  "r"(b00), "r"(b01));
            asm volatile(
                "mma.sync.aligned.m16n8k16.row.col.f32.bf16.bf16.f32 "
                "{%0,%1,%2,%3}, {%4,%5,%6,%7}, {%8,%9}, {%0,%1,%2,%3};"
                : "+f"(d0), "+f"(d1), "+f"(d2v), "+f"(d3)
                : "r"(a[rb][1][0]), "r"(a[rb][1][1]), "r"(a[rb][1][2]), "r"(a[rb][1][3]),
                  "r"(b10), "r"(b11));

            mn0 = fminf(mn0, fmaf(-2.0f, d0, sa0[rb] + sb.x));
            mn1 = fminf(mn1, fmaf(-2.0f, d1, sa0[rb] + sb.y));
            mn2 = fminf(mn2, fmaf(-2.0f, d2v, sa1[rb] + sb.x));
            mn3 = fminf(mn3, fmaf(-2.0f, d3, sa1[rb] + sb.y));
        }
    }
    float qmin = fminf(fminf(mn0, mn1), fminf(mn2, mn3));

    float acc = 0.0f;
    if (qmin < 4.0f) {
        // rare path: recompute with full hinge (deterministic MMAs)
#pragma unroll 1
        for (int nt = 0; nt < 16; nt++) {
            unsigned b00, b01, b10, b11;
            asm volatile(
                "ldmatrix.sync.aligned.m8n8.x4.shared.b16 {%0,%1,%2,%3}, [%4];"
                : "=r"(b00), "=r"(b01), "=r"(b10), "=r"(b11)
                : "r"(baddr + (unsigned)(nt * 8 * 80)));
            float2 sb = *(const float2*)&sqb[cb0 + nt * 8 + 2 * tq];
#pragma unroll
            for (int rb = 0; rb < 2; rb++) {
                float d0 = 0.0f, d1 = 0.0f, d2v = 0.0f, d3 = 0.0f;
                asm volatile(
                    "mma.sync.aligned.m16n8k16.row.col.f32.bf16.bf16.f32 "
                    "{%0,%1,%2,%3}, {%4,%5,%6,%7}, {%8,%9}, {%0,%1,%2,%3};"
                    : "+f"(d0), "+f"(d1), "+f"(d2v), "+f"(d3)
                    : "r"(a[rb][0][0]), "r"(a[rb][0][1]), "r"(a[rb][0][2]), "r"(a[rb][0][3]),
                      "r"(b00), "r"(b01));
                asm volatile(
                    "mma.sync.aligned.m16n8k16.row.col.f32.bf16.bf16.f32 "
                    "{%0,%1,%2,%3}, {%4,%5,%6,%7}, {%8,%9}, {%0,%1,%2,%3};"
                    : "+f"(d0), "+f"(d1), "+f"(d2v), "+f"(d3)
                    : "r"(a[rb][1][0]), "r"(a[rb][1][1]), "r"(a[rb][1][2]), "r"(a[rb][1][3]),
                      "r"(b10), "r"(b11));

                float q00 = fmaf(-2.0f, d0, sa0[rb] + sb.x);
                float q01 = fmaf(-2.0f, d1, sa0[rb] + sb.y);
                float q10 = fmaf(-2.0f, d2v, sa1[rb] + sb.x);
                float q11 = fmaf(-2.0f, d3, sa1[rb] + sb.y);
                float h0 = fmaxf(2.0f - sqrtf(fmaxf(q00, 0.0f) + 1e-12f), 0.0f);
                float h1 = fmaxf(2.0f - sqrtf(fmaxf(q01, 0.0f) + 1e-12f), 0.0f);
                float h2 = fmaxf(2.0f - sqrtf(fmaxf(q10, 0.0f) + 1e-12f), 0.0f);
                float h3 = fmaxf(2.0f - sqrtf(fmaxf(q11, 0.0f) + 1e-12f), 0.0f);
                acc += h0 * h0 + h1 * h1 + h2 * h2 + h3 * h3;
            }
        }
    }

#pragma unroll
    for (int o = 16; o > 0; o >>= 1) acc += __shfl_xor_sync(0xffffffffu, acc, o);
    if (lane == 0) wred[wid] = acc;
    __syncthreads();
    if (t == 0) {
        float s = 0.0f;
#pragma unroll
        for (int w2 = 0; w2 < 8; w2++) s += wred[w2];
        g_edge_part[id] = s;
    }

    // -------------------- ticket + last-block finalize ------------------------
    __threadfence();
    if (t == 0) {
        int old = atomicAdd(&g_ticket, 1);
        s_last = (old == PAIR_BLKS - 1);
    }
    __syncthreads();
    if (!s_last) return;

    __shared__ float fv[8], fe[8];
    __shared__ float smm[NI][CC];
    __shared__ float sM2[NI];
    __shared__ float sdist;

    float vs = 0.0f, es = 0.0f;
#pragma unroll
    for (int k = 0; k < VAR_BLKS / 256; k++) vs += g_var_part[t + k * 256];
#pragma unroll
    for (int k = 0; k < 4; k++) {
        int idx = t + k * 256;
        if (idx < PAIR_BLKS) es += g_edge_part[idx];
    }
#pragma unroll
    for (int o = 16; o > 0; o >>= 1) {
        vs += __shfl_xor_sync(0xffffffffu, vs, o);
        es += __shfl_xor_sync(0xffffffffu, es, o);
    }
    if (lane == 0) { fv[wid] = vs; fe[wid] = es; }

    float dist_tot = 0.0f, reg_tot = 0.0f;
    for (int bb2 = 0; bb2 < BB; bb2++) {
        int n = wid, c = lane;
        float mean = g_sums[bb2][n][c] / g_counts[bb2][n];
        smm[n][c] = mean;
        if (t == 0) sdist = 0.0f;
        float m2 = mean * mean;
#pragma unroll
        for (int o = 16; o > 0; o >>= 1) m2 += __shfl_xor_sync(0xffffffffu, m2, o);
        if (lane == 0) sM2[n] = m2;
        __syncthreads();
        if (t < NPAIRS) {
            int ii = 0, rem2 = t;
            while (rem2 >= (NI - 1) - ii) { rem2 -= (NI - 1) - ii; ii++; }
            int jj = ii + 1 + rem2;
            float dd2 = 0.0f;
#pragma unroll
            for (int cc2 = 0; cc2 < CC; cc2++) {
                float df = smm[ii][cc2] - smm[jj][cc2];
                dd2 += df * df;
            }
            float dm = sqrtf(fmaxf(dd2, 0.0f) + 1e-12f);
            float h = fmaxf(3.0f - dm, 0.0f);   // 2*DD
            atomicAdd(&sdist, h * h);
        }
        __syncthreads();
        if (t == 0) {
            float r = 0.0f;
#pragma unroll
            for (int nn = 0; nn < NI; nn++)
                r += sqrtf(fmaxf(sM2[nn], 0.0f) + 1e-12f);
            reg_tot  += r * (1.0f / (float)NI);
            dist_tot += sdist;
        }
        __syncthreads();
    }

    // clear stats scratch + barriers for next replay
    {
        float* s4 = &g_sums[0][0][0];
        s4[t] = 0.0f; s4[t + 256] = 0.0f; s4[t + 512] = 0.0f; s4[t + 768] = 0.0f;
        if (t < BB * NI) (&g_counts[0][0])[t] = 0.0f;
    }

    if (t == 0) {
        float V = 0.0f, E = 0.0f;
#pragma unroll
        for (int w2 = 0; w2 < 8; w2++) { V += fv[w2]; E += fe[w2]; }
        float var  = V * (1.0f / (float)NI);
        float dist = dist_tot * (1.0f / 56.0f);
        float edge = E * (1.0f / (512.0f * 512.0f * 56.0f));
        float reg  = 0.001f * reg_tot;
        out[0] = var + dist + edge + reg;
        out[1] = var;
        out[2] = dist;
        out[3] = edge;
        out[4] = reg;
        g_ticket = 0;
        g_selbar = 0;
    }
}

// ------------------------------------------------------------------ launcher
extern "C" void kernel_launch(void* const* d_in, const int* in_sizes, int n_in,
                              void* d_out, int out_size) {
    const float* features   = (const float*)d_in[0];
    const int*   labels     = (const int*)d_in[1];
    const int*   labelEdges = (const int*)d_in[2];
    float* out = (float*)d_out;
    (void)in_sizes; (void)n_in; (void)out_size;

    kSelW<<<SEL_BLKS, 256>>>(labelEdges);
    kStats<<<STATS_BLKS, 512>>>(features, labels);
    kC<<<KC_BLKS, 256>>>(features, labels);
    kD<<<PAIR_BLKS, 256>>>(out);
}

// round 15
// speedup vs baseline: 1.0422x; 1.0422x over previous
#include <cuda_runtime.h>
#include <cuda_bf16.h>
#include <cstdint>
#include <math.h>

#define BB 4
#define CC 32
#define PP 262144
#define NI 8
#define EE 512
#define NPTS 4096
#define NPAIRS 28

#define NCHUNK_SEL 32
#define CHPX_SEL (PP / NCHUNK_SEL)     // 8192
#define SEL_BLKS (BB * NCHUNK_SEL)     // 128 (< 148 SMs: all wave-1 resident)
#define STATS_BLKS (BB * 128)          // 512 blocks x 512 threads x 2048 px
#define GATH_BLKS 256
#define VAR_BLKS 1024
#define KC_BLKS (GATH_BLKS + VAR_BLKS)
#define PAIR_BLKS (BB * NPAIRS * 8)    // 896

// ---------------- device scratch (static globals; no allocations) -------------
__device__ float g_sums[BB][NI][CC];
__device__ float g_counts[BB][NI];
__device__ int   g_cnt[BB][NCHUNK_SEL][NI];
__device__ int   g_sel[BB][NI][EE];
__device__ __align__(16) __nv_bfloat16 g_ebh[BB][NPTS][CC];
__device__ float g_sq[BB][NPTS];
__device__ float g_var_part[VAR_BLKS];
__device__ float g_edge_part[PAIR_BLKS];
__device__ int   g_selbar;   // sel-phase barrier (reset by kD finalize)
__device__ int   g_ticket;   // kD finalize ticket (reset by kD finalize)

// ====== kSelW: count + grid barrier + ranked write (128 blocks, 1 launch) =====
__global__ __launch_bounds__(256) void kSelW(const int* __restrict__ labelEdges) {
    int t = threadIdx.x;
    int lane = t & 31, wid = t >> 5;
    int b = blockIdx.x >> 5;
    int chunk = blockIdx.x & 31;
    const int* le = labelEdges + (size_t)b * PP + chunk * CHPX_SEL;
    int start = t * 32;

    // -------- phase 1: count own chunk per instance ---------------------------
    int cnt[NI];
#pragma unroll
    for (int n = 0; n < NI; n++) cnt[n] = 0;
#pragma unroll
    for (int k = 0; k < 8; k++) {
        int4 q = *(const int4*)&le[start + k * 4];
#pragma unroll
        for (int n = 0; n < NI; n++)
            cnt[n] += (q.x == n) + (q.y == n) + (q.z == n) + (q.w == n);
    }

    // warp inclusive scans + cross-warp prefixes (reused for phase 2)
    __shared__ int wtot[8][NI];
    int inc[NI];
#pragma unroll
    for (int n = 0; n < NI; n++) {
        int v = cnt[n];
#pragma unroll
        for (int off = 1; off < 32; off <<= 1) {
            int u = __shfl_up_sync(0xffffffffu, v, off);
            if (lane >= off) v += u;
        }
        inc[n] = v;
        if (lane == 31) wtot[wid][n] = v;
    }
    __syncthreads();
    __shared__ int wpre[8][NI];
    if (t < 64) {
        int w2 = t >> 3, n = t & 7;
        int s = 0;
        for (int w = 0; w < w2; w++) s += wtot[w][n];
        wpre[w2][n] = s;
    }
    __syncthreads();
    if (t < NI) g_cnt[b][chunk][t] = wpre[7][t] + wtot[7][t];

    // -------- grid barrier (all 128 blocks are resident) ----------------------
    __threadfence();
    __syncthreads();
    if (t == 0) {
        atomicAdd(&g_selbar, 1);
        volatile int* vp = &g_selbar;
        while (*vp < SEL_BLKS) __nanosleep(32);
    }
    __syncthreads();
    __threadfence();

    // -------- phase 2: ranked write -------------------------------------------
    __shared__ int spre[NI];
    if (t < NI) {
        int s = 0;
        for (int c = 0; c < chunk; c++) s += g_cnt[b][c][t];
        spre[t] = s;
    }
    __syncthreads();
    bool any = false;
#pragma unroll
    for (int n = 0; n < NI; n++) any |= (spre[n] < EE);
    if (!any) return;

    int rank[NI];
#pragma unroll
    for (int n = 0; n < NI; n++)
        rank[n] = spre[n] + wpre[wid][n] + inc[n] - cnt[n];

#pragma unroll
    for (int k = 0; k < 8; k++) {
        int4 q = *(const int4*)&le[start + k * 4];
        int p = chunk * CHPX_SEL + start + k * 4;
        int l0 = q.x, l1 = q.y, l2 = q.z, l3 = q.w;
        if (rank[l0] < EE) g_sel[b][l0][rank[l0]] = p;     rank[l0]++;
        if (rank[l1] < EE) g_sel[b][l1][rank[l1]] = p + 1; rank[l1]++;
        if (rank[l2] < EE) g_sel[b][l2][rank[l2]] = p + 2; rank[l2]++;
        if (rank[l3] < EE) g_sel[b][l3][rank[l3]] = p + 3; rank[l3]++;
    }
}

// ========== kStats: label sums + counts (512 thr, 2 ch/warp, low regs) ========
__global__ __launch_bounds__(512, 2) void kStats(const float* __restrict__ feat,
                                                 const int* __restrict__ labels) {
    int b = blockIdx.x >> 7;
    int chunk = blockIdx.x & 127;
    int base = chunk * 2048;
    const float* f = feat + (size_t)b * CC * PP;
    const int* lb = labels + (size_t)b * PP;
    int t = threadIdx.x;
    int lane = t & 31, wid = t >> 5;   // 16 warps

    __shared__ int slab[2048];
    *(int4*)&slab[t * 4] = *(const int4*)&lb[base + t * 4];
    __syncthreads();

    int c0 = wid * 2;                  // warp owns channels c0, c0+1
    float acc[NI][2];
#pragma unroll
    for (int n = 0; n < NI; n++) { acc[n][0] = 0.0f; acc[n][1] = 0.0f; }

#pragma unroll
    for (int it = 0; it < 16; it++) {
        int pofs = it * 128 + lane * 4;
        const float* fp = f + base + pofs;
        float4 va = *(const float4*)&fp[(size_t)(c0 + 0) * PP];
        float4 vb = *(const float4*)&fp[(size_t)(c0 + 1) * PP];
        int l[4] = { slab[pofs], slab[pofs + 1], slab[pofs + 2], slab[pofs + 3] };
        float vA[4] = { va.x, va.y, va.z, va.w };
        float vB[4] = { vb.x, vb.y, vb.z, vb.w };
#pragma unroll
        for (int j = 0; j < 4; j++) {
#pragma unroll
            for (int n = 0; n < NI; n++) {
                float m = (l[j] == n) ? 1.0f : 0.0f;
                acc[n][0] = fmaf(m, vA[j], acc[n][0]);
                acc[n][1] = fmaf(m, vB[j], acc[n][1]);
            }
        }
    }

#pragma unroll
    for (int n = 0; n < NI; n++)
#pragma unroll
        for (int e = 0; e < 2; e++) {
            float a = acc[n][e];
#pragma unroll
            for (int o = 16; o > 0; o >>= 1) a += __shfl_xor_sync(0xffffffffu, a, o);
            acc[n][e] = a;
        }
    if (lane == 0) {
#pragma unroll
        for (int n = 0; n < NI; n++) {
            atomicAdd(&g_sums[b][n][c0 + 0], acc[n][0]);
            atomicAdd(&g_sums[b][n][c0 + 1], acc[n][1]);
        }
    }

    if (wid == 0) {
        int cnt[NI];
#pragma unroll
        for (int n = 0; n < NI; n++) cnt[n] = 0;
        for (int i = lane; i < 2048; i += 32) {
            int l = slab[i];
#pragma unroll
            for (int n = 0; n < NI; n++) cnt[n] += (l == n);
        }
#pragma unroll
        for (int n = 0; n < NI; n++) {
            int a = cnt[n];
#pragma unroll
            for (int o = 16; o > 0; o >>= 1) a += __shfl_xor_sync(0xffffffffu, a, o);
            cnt[n] = a;
        }
        if (lane == 0) {
#pragma unroll
            for (int n = 0; n < NI; n++)
                atomicAdd(&g_counts[b][n], (float)cnt[n]);
        }
    }
}

// ==================== kC: gather (256 blks) + var (1024) ======================
__global__ __launch_bounds__(256) void kC(const float* __restrict__ feat,
                                          const int* __restrict__ labels) {
    int t = threadIdx.x;
    int lane = t & 31, wid = t >> 5;

    if (blockIdx.x < GATH_BLKS) {
        int gidx = blockIdx.x * 256 + t;
        int b = gidx >> 14;
        int r = gidx & 16383;
        int pt = r >> 2;
        int cg = r & 3;
        int inst = pt >> 9;
        int e = pt & (EE - 1);
        int idx = g_sel[b][inst][e];
        const float* f = feat + (size_t)b * CC * PP;

        float sq = 0.0f;
        unsigned pk[4];
#pragma unroll
        for (int k = 0; k < 4; k++) {
            float va = f[(size_t)(cg * 8 + 2 * k) * PP + idx];
            float vb = f[(size_t)(cg * 8 + 2 * k + 1) * PP + idx];
            sq += va * va + vb * vb;
            __nv_bfloat162 h = __floats2bfloat162_rn(va, vb);
            pk[k] = *reinterpret_cast<unsigned*>(&h);
        }
        *(uint4*)&g_ebh[b][pt][cg * 8] = make_uint4(pk[0], pk[1], pk[2], pk[3]);

        sq += __shfl_xor_sync(0xffffffffu, sq, 1);
        sq += __shfl_xor_sync(0xffffffffu, sq, 2);
        if (cg == 0) g_sq[b][pt] = sq;
        return;
    }

    int vb2 = blockIdx.x - GATH_BLKS;
    int b = vb2 >> 8;
    int chunk = vb2 & 255;
    int base = chunk * 1024;
    const float* f = feat + (size_t)b * CC * PP;
    const int* lb = labels + (size_t)b * PP;

    __shared__ float sm[NI * 36];
    __shared__ float sinv[NI];
    __shared__ float wred[8];
    {
        int n = wid, c = lane;
        float cntv = g_counts[b][n];
        sm[n * 36 + c] = g_sums[b][n][c] / cntv;
        if (c == 0) sinv[n] = 1.0f / cntv;
    }
    __syncthreads();

    int p4 = base + t * 4;
    int4 L = *(const int4*)&lb[p4];
    int lv[4] = { L.x, L.y, L.z, L.w };

    float d2[4] = { 0.0f, 0.0f, 0.0f, 0.0f };
#pragma unroll
    for (int cg = 0; cg < 8; cg++) {
        float4 v0 = *(const float4*)&f[(size_t)(cg * 4 + 0) * PP + p4];
        float4 v1 = *(const float4*)&f[(size_t)(cg * 4 + 1) * PP + p4];
        float4 v2 = *(const float4*)&f[(size_t)(cg * 4 + 2) * PP + p4];
        float4 v3 = *(const float4*)&f[(size_t)(cg * 4 + 3) * PP + p4];
        float vj[4][4] = { {v0.x, v1.x, v2.x, v3.x},
                           {v0.y, v1.y, v2.y, v3.y},
                           {v0.z, v1.z, v2.z, v3.z},
                           {v0.w, v1.w, v2.w, v3.w} };
#pragma unroll
        for (int j = 0; j < 4; j++) {
            float4 m = *(const float4*)&sm[lv[j] * 36 + cg * 4];
            float t0 = vj[j][0] - m.x;
            float t1 = vj[j][1] - m.y;
            float t2 = vj[j][2] - m.z;
            float t3 = vj[j][3] - m.w;
            d2[j] += t0 * t0 + t1 * t1 + t2 * t2 + t3 * t3;
        }
    }

    float hsum = 0.0f;
#pragma unroll
    for (int j = 0; j < 4; j++) {
        float d = sqrtf(d2[j] + 1e-12f);
        float h = fmaxf(d - 0.5f, 0.0f);          // DV = 0.5
        hsum += h * h * sinv[lv[j]];
    }
#pragma unroll
    for (int o = 16; o > 0; o >>= 1) hsum += __shfl_xor_sync(0xffffffffu, hsum, o);
    if (lane == 0) wred[wid] = hsum;
    __syncthreads();
    if (t == 0) {
        float s = 0.0f;
#pragma unroll
        for (int w2 = 0; w2 < 8; w2++) s += wred[w2];
        g_var_part[vb2] = s;
    }
}

// ========== kD: pairs (mma, 128x256, hoisted rare-path) + finalize ============
__global__ __launch_bounds__(256) void kD(float* __restrict__ out) {
    __shared__ __align__(16) __nv_bfloat16 As[128][40];
    __shared__ __align__(16) __nv_bfloat16 Bs[256][40];
    __shared__ float sqa[128];
    __shared__ __align__(8) float sqb[256];
    __shared__ float wred[8];
    __shared__ int s_last;

    int t = threadIdx.x;
    int lane = t & 31, wid = t >> 5;

    int id = blockIdx.x;
    int b = id / (NPAIRS * 8);
    int r2 = id % (NPAIRS * 8);
    int pair = r2 >> 3;
    int tile = r2 & 7;
    int i = 0, rem = pair;
    while (rem >= (NI - 1) - i) { rem -= (NI - 1) - i; i++; }
    int j = i + 1 + rem;
    int ti = tile >> 1, tj = tile & 1;
    int i0 = i * EE + ti * 128;
    int j0 = j * EE + tj * 256;

    {
        int row4 = t >> 2, ch8 = (t & 3) * 8;
#pragma unroll
        for (int rr = 0; rr < 2; rr++)
            *(uint4*)&As[row4 + rr * 64][ch8] =
                *(const uint4*)&g_ebh[b][i0 + row4 + rr * 64][ch8];
#pragma unroll
        for (int rr = 0; rr < 4; rr++)
            *(uint4*)&Bs[row4 + rr * 64][ch8] =
                *(const uint4*)&g_ebh[b][j0 + row4 + rr * 64][ch8];
    }
    if (t < 128) sqa[t] = g_sq[b][i0 + t];
    sqb[t] = g_sq[b][j0 + t];
    __syncthreads();

    int wi = wid >> 1, wj = wid & 1;
    int r0 = wi * 32, cb0 = wj * 128;
    int g = lane >> 2, tq = lane & 3;

    unsigned a[2][2][4];
#pragma unroll
    for (int rb = 0; rb < 2; rb++)
#pragma unroll
        for (int ks = 0; ks < 2; ks++) {
            int rbase = r0 + rb * 16;
            int kb = ks * 16 + 2 * tq;
            a[rb][ks][0] = *(const unsigned*)&As[rbase + g][kb];
            a[rb][ks][1] = *(const unsigned*)&As[rbase + g + 8][kb];
            a[rb][ks][2] = *(const unsigned*)&As[rbase + g][kb + 8];
            a[rb][ks][3] = *(const unsigned*)&As[rbase + g + 8][kb + 8];
        }
    float sa0[2] = { sqa[r0 + g],     sqa[r0 + 16 + g] };
    float sa1[2] = { sqa[r0 + 8 + g], sqa[r0 + 24 + g] };

    unsigned bs_u32 = (unsigned)__cvta_generic_to_shared(&Bs[0][0]);
    unsigned baddr = bs_u32 +
        (unsigned)(((cb0 + (lane & 7)) * 40 + (lane >> 3) * 8) * 2);

    float mn0 = 1e30f, mn1 = 1e30f, mn2 = 1e30f, mn3 = 1e30f;
#pragma unroll
    for (int nt = 0; nt < 16; nt++) {
        unsigned b00, b01, b10, b11;
        asm volatile(
            "ldmatrix.sync.aligned.m8n8.x4.shared.b16 {%0,%1,%2,%3}, [%4];"
            : "=r"(b00), "=r"(b01), "=r"(b10), "=r"(b11)
            : "r"(baddr + (unsigned)(nt * 8 * 80)));
        float2 sb = *(const float2*)&sqb[cb0 + nt * 8 + 2 * tq];
#pragma unroll
        for (int rb = 0; rb < 2; rb++) {
            float d0 = 0.0f, d1 = 0.0f, d2v = 0.0f, d3 = 0.0f;
            asm volatile(
                "mma.sync.aligned.m16n8k16.row.col.f32.bf16.bf16.f32 "
                "{%0,%1,%2,%3}, {%4,%5,%6,%7}, {%8,%9}, {%0,%1,%2,%3};"
                : "+f"(d0), "+f"(d1), "+f"(d2v), "+f"(d3)
                : "r"(a[rb][0][0]), "r"(a[rb][0][1]), "r"(a[rb][0][2]), "r"(a[rb][0][3]),
                  "r"(b00), "r"(b01));
            asm volatile(
                "mma.sync.aligned.m16n8k16.row.col.f32.bf16.bf16.f32 "
                "{%0,%1,%2,%3}, {%4,%5,%6,%7}, {%8,%9}, {%0,%1,%2,%3};"
                : "+f"(d0), "+f"(d1), "+f"(d2v), "+f"(d3)
                : "r"(a[rb][1][0]), "r"(a[rb][1][1]), "r"(a[rb][1][2]), "r"(a[rb][1][3]),
                  "r"(b10), "r"(b11));

            mn0 = fminf(mn0, fmaf(-2.0f, d0, sa0[rb] + sb.x));
            mn1 = fminf(mn1, fmaf(-2.0f, d1, sa0[rb] + sb.y));
            mn2 = fminf(mn2, fmaf(-2.0f, d2v, sa1[rb] + sb.x));
            mn3 = fminf(mn3, fmaf(-2.0f, d3, sa1[rb] + sb.y));
        }
    }
    float qmin = fminf(fminf(mn0, mn1), fminf(mn2, mn3));

    float acc = 0.0f;
    if (qmin < 4.0f) {
        // rare path: recompute with full hinge (deterministic MMAs)
#pragma unroll 1
        for (int nt = 0; nt < 16; nt++) {
            unsigned b00, b01, b10, b11;
            asm volatile(
                "ldmatrix.sync.aligned.m8n8.x4.shared.b16 {%0,%1,%2,%3}, [%4];"
                : "=r"(b00), "=r"(b01), "=r"(b10), "=r"(b11)
                : "r"(baddr + (unsigned)(nt * 8 * 80)));
            float2 sb = *(const float2*)&sqb[cb0 + nt * 8 + 2 * tq];
#pragma unroll
            for (int rb = 0; rb < 2; rb++) {
                float d0 = 0.0f, d1 = 0.0f, d2v = 0.0f, d3 = 0.0f;
                asm volatile(
                    "mma.sync.aligned.m16n8k16.row.col.f32.bf16.bf16.f32 "
                    "{%0,%1,%2,%3}, {%4,%5,%6,%7}, {%8,%9}, {%0,%1,%2,%3};"
                    : "+f"(d0), "+f"(d1), "+f"(d2v), "+f"(d3)
                    : "r"(a[rb][0][0]), "r"(a[rb][0][1]), "r"(a[rb][0][2]), "r"(a[rb][0][3]),
                      "r"(b00), "r"(b01));
                asm volatile(
                    "mma.sync.aligned.m16n8k16.row.col.f32.bf16.bf16.f32 "
                    "{%0,%1,%2,%3}, {%4,%5,%6,%7}, {%8,%9}, {%0,%1,%2,%3};"
                    : "+f"(d0), "+f"(d1), "+f"(d2v), "+f"(d3)
                    : "r"(a[rb][1][0]), "r"(a[rb][1][1]), "r"(a[rb][1][2]), "r"(a[rb][1][3]),
                      "r"(b10), "r"(b11));

                float q00 = fmaf(-2.0f, d0, sa0[rb] + sb.x);
                float q01 = fmaf(-2.0f, d1, sa0[rb] + sb.y);
                float q10 = fmaf(-2.0f, d2v, sa1[rb] + sb.x);
                float q11 = fmaf(-2.0f, d3, sa1[rb] + sb.y);
                float h0 = fmaxf(2.0f - sqrtf(fmaxf(q00, 0.0f) + 1e-12f), 0.0f);
                float h1 = fmaxf(2.0f - sqrtf(fmaxf(q01, 0.0f) + 1e-12f), 0.0f);
                float h2 = fmaxf(2.0f - sqrtf(fmaxf(q10, 0.0f) + 1e-12f), 0.0f);
                float h3 = fmaxf(2.0f - sqrtf(fmaxf(q11, 0.0f) + 1e-12f), 0.0f);
                acc += h0 * h0 + h1 * h1 + h2 * h2 + h3 * h3;
            }
        }
    }

#pragma unroll
    for (int o = 16; o > 0; o >>= 1) acc += __shfl_xor_sync(0xffffffffu, acc, o);
    if (lane == 0) wred[wid] = acc;
    __syncthreads();
    if (t == 0) {
        float s = 0.0f;
#pragma unroll
        for (int w2 = 0; w2 < 8; w2++) s += wred[w2];
        g_edge_part[id] = s;
    }

    // -------------------- ticket + last-block finalize ------------------------
    __threadfence();
    if (t == 0) {
        int old = atomicAdd(&g_ticket, 1);
        s_last = (old == PAIR_BLKS - 1);
    }
    __syncthreads();
    if (!s_last) return;

    __shared__ float fv[8], fe[8];
    __shared__ float smm[NI][CC];
    __shared__ float sM2[NI];
    __shared__ float sdist;

    float vs = 0.0f, es = 0.0f;
#pragma unroll
    for (int k = 0; k < VAR_BLKS / 256; k++) vs += g_var_part[t + k * 256];
#pragma unroll
    for (int k = 0; k < 4; k++) {
        int idx = t + k * 256;
        if (idx < PAIR_BLKS) es += g_edge_part[idx];
    }
#pragma unroll
    for (int o = 16; o > 0; o >>= 1) {
        vs += __shfl_xor_sync(0xffffffffu, vs, o);
        es += __shfl_xor_sync(0xffffffffu, es, o);
    }
    if (lane == 0) { fv[wid] = vs; fe[wid] = es; }

    float dist_tot = 0.0f, reg_tot = 0.0f;
    for (int bb2 = 0; bb2 < BB; bb2++) {
        int n = wid, c = lane;
        float mean = g_sums[bb2][n][c] / g_counts[bb2][n];
        smm[n][c] = mean;
        if (t == 0) sdist = 0.0f;
        float m2 = mean * mean;
#pragma unroll
        for (int o = 16; o > 0; o >>= 1) m2 += __shfl_xor_sync(0xffffffffu, m2, o);
        if (lane == 0) sM2[n] = m2;
        __syncthreads();
        if (t < NPAIRS) {
            int ii = 0, rem2 = t;
            while (rem2 >= (NI - 1) - ii) { rem2 -= (NI - 1) - ii; ii++; }
            int jj = ii + 1 + rem2;
            float dd2 = 0.0f;
#pragma unroll
            for (int cc2 = 0; cc2 < CC; cc2++) {
                float df = smm[ii][cc2] - smm[jj][cc2];
                dd2 += df * df;
            }
            float dm = sqrtf(fmaxf(dd2, 0.0f) + 1e-12f);
            float h = fmaxf(3.0f - dm, 0.0f);   // 2*DD
            atomicAdd(&sdist, h * h);
        }
        __syncthreads();
        if (t == 0) {
            float r = 0.0f;
#pragma unroll
            for (int nn = 0; nn < NI; nn++)
                r += sqrtf(fmaxf(sM2[nn], 0.0f) + 1e-12f);
            reg_tot  += r * (1.0f / (float)NI);
            dist_tot += sdist;
        }
        __syncthreads();
    }

    // clear stats scratch + barriers for next replay
    {
        float* s4 = &g_sums[0][0][0];
        s4[t] = 0.0f; s4[t + 256] = 0.0f; s4[t + 512] = 0.0f; s4[t + 768] = 0.0f;
        if (t < BB * NI) (&g_counts[0][0])[t] = 0.0f;
    }

    if (t == 0) {
        float V = 0.0f, E = 0.0f;
#pragma unroll
        for (int w2 = 0; w2 < 8; w2++) { V += fv[w2]; E += fe[w2]; }
        float var  = V * (1.0f / (float)NI);
        float dist = dist_tot * (1.0f / 56.0f);
        float edge = E * (1.0f / (512.0f * 512.0f * 56.0f));
        float reg  = 0.001f * reg_tot;
        out[0] = var + dist + edge + reg;
        out[1] = var;
        out[2] = dist;
        out[3] = edge;
        out[4] = reg;
        g_ticket = 0;
        g_selbar = 0;
    }
}

// ------------------------------------------------------------------ launcher
extern "C" void kernel_launch(void* const* d_in, const int* in_sizes, int n_in,
                              void* d_out, int out_size) {
    const float* features   = (const float*)d_in[0];
    const int*   labels     = (const int*)d_in[1];
    const int*   labelEdges = (const int*)d_in[2];
    float* out = (float*)d_out;
    (void)in_sizes; (void)n_in; (void)out_size;

    kSelW<<<SEL_BLKS, 256>>>(labelEdges);
    kStats<<<STATS_BLKS, 512>>>(features, labels);
    kC<<<KC_BLKS, 256>>>(features, labels);
    kD<<<PAIR_BLKS, 256>>>(out);
}

// round 16
// speedup vs baseline: 1.0647x; 1.0216x over previous
#include <cuda_runtime.h>
#include <cuda_bf16.h>
#include <cstdint>
#include <math.h>

#define BB 4
#define CC 32
#define PP 262144
#define NI 8
#define EE 512
#define NPTS 4096
#define NPAIRS 28

#define NCHUNK_SEL 32
#define CHPX_SEL (PP / NCHUNK_SEL)     // 8192
#define SEL_BLKS (BB * NCHUNK_SEL)     // 128 (< 148 SMs: all wave-1 resident)
#define STATS_BLKS (BB * 128)          // 512 blocks x 512 threads x 2048 px
#define GATH_BLKS 256
#define VAR_BLKS 1024
#define PAIR_BLKS (BB * NPAIRS * 8)    // 896
#define KVP_BLKS (VAR_BLKS + PAIR_BLKS)  // 1920

// ---------------- device scratch (static globals; no allocations) -------------
__device__ float g_sums[BB][NI][CC];
__device__ float g_counts[BB][NI];
__device__ int   g_cnt[BB][NCHUNK_SEL][NI];
__device__ int   g_sel[BB][NI][EE];
__device__ __align__(16) __nv_bfloat16 g_ebh[BB][NPTS][CC];
__device__ float g_sq[BB][NPTS];
__device__ float g_var_part[VAR_BLKS];
__device__ float g_edge_part[PAIR_BLKS];
__device__ int   g_selbar;   // sel-phase barrier (reset by finalize)
__device__ int   g_ticket;   // kVP finalize ticket (reset by finalize)

// ====== kSelW: count + grid barrier + ranked write (128 blocks, 1 launch) =====
__global__ __launch_bounds__(256) void kSelW(const int* __restrict__ labelEdges) {
    int t = threadIdx.x;
    int lane = t & 31, wid = t >> 5;
    int b = blockIdx.x >> 5;
    int chunk = blockIdx.x & 31;
    const int* le = labelEdges + (size_t)b * PP + chunk * CHPX_SEL;
    int start = t * 32;

    int cnt[NI];
#pragma unroll
    for (int n = 0; n < NI; n++) cnt[n] = 0;
#pragma unroll
    for (int k = 0; k < 8; k++) {
        int4 q = *(const int4*)&le[start + k * 4];
#pragma unroll
        for (int n = 0; n < NI; n++)
            cnt[n] += (q.x == n) + (q.y == n) + (q.z == n) + (q.w == n);
    }

    __shared__ int wtot[8][NI];
    int inc[NI];
#pragma unroll
    for (int n = 0; n < NI; n++) {
        int v = cnt[n];
#pragma unroll
        for (int off = 1; off < 32; off <<= 1) {
            int u = __shfl_up_sync(0xffffffffu, v, off);
            if (lane >= off) v += u;
        }
        inc[n] = v;
        if (lane == 31) wtot[wid][n] = v;
    }
    __syncthreads();
    __shared__ int wpre[8][NI];
    if (t < 64) {
        int w2 = t >> 3, n = t & 7;
        int s = 0;
        for (int w = 0; w < w2; w++) s += wtot[w][n];
        wpre[w2][n] = s;
    }
    __syncthreads();
    if (t < NI) g_cnt[b][chunk][t] = wpre[7][t] + wtot[7][t];

    __threadfence();
    __syncthreads();
    if (t == 0) {
        atomicAdd(&g_selbar, 1);
        volatile int* vp = &g_selbar;
        while (*vp < SEL_BLKS) __nanosleep(32);
    }
    __syncthreads();
    __threadfence();

    __shared__ int spre[NI];
    if (t < NI) {
        int s = 0;
        for (int c = 0; c < chunk; c++) s += g_cnt[b][c][t];
        spre[t] = s;
    }
    __syncthreads();
    bool any = false;
#pragma unroll
    for (int n = 0; n < NI; n++) any |= (spre[n] < EE);
    if (!any) return;

    int rank[NI];
#pragma unroll
    for (int n = 0; n < NI; n++)
        rank[n] = spre[n] + wpre[wid][n] + inc[n] - cnt[n];

#pragma unroll
    for (int k = 0; k < 8; k++) {
        int4 q = *(const int4*)&le[start + k * 4];
        int p = chunk * CHPX_SEL + start + k * 4;
        int l0 = q.x, l1 = q.y, l2 = q.z, l3 = q.w;
        if (rank[l0] < EE) g_sel[b][l0][rank[l0]] = p;     rank[l0]++;
        if (rank[l1] < EE) g_sel[b][l1][rank[l1]] = p + 1; rank[l1]++;
        if (rank[l2] < EE) g_sel[b][l2][rank[l2]] = p + 2; rank[l2]++;
        if (rank[l3] < EE) g_sel[b][l3][rank[l3]] = p + 3; rank[l3]++;
    }
}

// ========== kStats: label sums + counts (512 thr, 2 ch/warp, low regs) ========
__global__ __launch_bounds__(512, 2) void kStats(const float* __restrict__ feat,
                                                 const int* __restrict__ labels) {
    int b = blockIdx.x >> 7;
    int chunk = blockIdx.x & 127;
    int base = chunk * 2048;
    const float* f = feat + (size_t)b * CC * PP;
    const int* lb = labels + (size_t)b * PP;
    int t = threadIdx.x;
    int lane = t & 31, wid = t >> 5;   // 16 warps

    __shared__ int slab[2048];
    *(int4*)&slab[t * 4] = *(const int4*)&lb[base + t * 4];
    __syncthreads();

    int c0 = wid * 2;
    float acc[NI][2];
#pragma unroll
    for (int n = 0; n < NI; n++) { acc[n][0] = 0.0f; acc[n][1] = 0.0f; }

#pragma unroll
    for (int it = 0; it < 16; it++) {
        int pofs = it * 128 + lane * 4;
        const float* fp = f + base + pofs;
        float4 va = *(const float4*)&fp[(size_t)(c0 + 0) * PP];
        float4 vb = *(const float4*)&fp[(size_t)(c0 + 1) * PP];
        int l[4] = { slab[pofs], slab[pofs + 1], slab[pofs + 2], slab[pofs + 3] };
        float vA[4] = { va.x, va.y, va.z, va.w };
        float vB[4] = { vb.x, vb.y, vb.z, vb.w };
#pragma unroll
        for (int j = 0; j < 4; j++) {
#pragma unroll
            for (int n = 0; n < NI; n++) {
                float m = (l[j] == n) ? 1.0f : 0.0f;
                acc[n][0] = fmaf(m, vA[j], acc[n][0]);
                acc[n][1] = fmaf(m, vB[j], acc[n][1]);
            }
        }
    }

#pragma unroll
    for (int n = 0; n < NI; n++)
#pragma unroll
        for (int e = 0; e < 2; e++) {
            float a = acc[n][e];
#pragma unroll
            for (int o = 16; o > 0; o >>= 1) a += __shfl_xor_sync(0xffffffffu, a, o);
            acc[n][e] = a;
        }
    if (lane == 0) {
#pragma unroll
        for (int n = 0; n < NI; n++) {
            atomicAdd(&g_sums[b][n][c0 + 0], acc[n][0]);
            atomicAdd(&g_sums[b][n][c0 + 1], acc[n][1]);
        }
    }

    if (wid == 0) {
        int cnt[NI];
#pragma unroll
        for (int n = 0; n < NI; n++) cnt[n] = 0;
        for (int i = lane; i < 2048; i += 32) {
            int l = slab[i];
#pragma unroll
            for (int n = 0; n < NI; n++) cnt[n] += (l == n);
        }
#pragma unroll
        for (int n = 0; n < NI; n++) {
            int a = cnt[n];
#pragma unroll
            for (int o = 16; o > 0; o >>= 1) a += __shfl_xor_sync(0xffffffffu, a, o);
            cnt[n] = a;
        }
        if (lane == 0) {
#pragma unroll
            for (int n = 0; n < NI; n++)
                atomicAdd(&g_counts[b][n], (float)cnt[n]);
        }
    }
}

// ============= kGath: gather edge features -> bf16 + squared norms ============
__global__ __launch_bounds__(256) void kGath(const float* __restrict__ feat) {
    int t = threadIdx.x;
    int gidx = blockIdx.x * 256 + t;
    int b = gidx >> 14;
    int r = gidx & 16383;
    int pt = r >> 2;
    int cg = r & 3;
    int inst = pt >> 9;
    int e = pt & (EE - 1);
    int idx = g_sel[b][inst][e];
    const float* f = feat + (size_t)b * CC * PP;

    float sq = 0.0f;
    unsigned pk[4];
#pragma unroll
    for (int k = 0; k < 4; k++) {
        float va = f[(size_t)(cg * 8 + 2 * k) * PP + idx];
        float vb = f[(size_t)(cg * 8 + 2 * k + 1) * PP + idx];
        sq += va * va + vb * vb;
        __nv_bfloat162 h = __floats2bfloat162_rn(va, vb);
        pk[k] = *reinterpret_cast<unsigned*>(&h);
    }
    *(uint4*)&g_ebh[b][pt][cg * 8] = make_uint4(pk[0], pk[1], pk[2], pk[3]);

    sq += __shfl_xor_sync(0xffffffffu, sq, 1);
    sq += __shfl_xor_sync(0xffffffffu, sq, 2);
    if (cg == 0) g_sq[b][pt] = sq;
}

// ===== kVP: var (blocks 0-1023) + pairs (1024-1919) + ticket finalize =========
struct VarS  { float sm[NI * 36]; float sinv[NI]; float wred[8]; };
struct PairS { unsigned short As[128][40]; unsigned short Bs[256][40];
               float sqa[128]; float sqb[256]; float wred[8]; };
struct FinS  { float fv[8]; float fe[8]; float smm[NI][CC]; float sM2[NI]; float sdist; };

__global__ __launch_bounds__(256) void kVP(const float* __restrict__ feat,
                                           const int* __restrict__ labels,
                                           float* __restrict__ out) {
    __shared__ __align__(16) unsigned char Sbuf[sizeof(PairS)];
    __shared__ int s_last;

    int t = threadIdx.x;
    int lane = t & 31, wid = t >> 5;

    if (blockIdx.x < VAR_BLKS) {
        // -------------------------- variance (pull) loss ----------------------
        VarS* V = reinterpret_cast<VarS*>(Sbuf);
        int vb2 = blockIdx.x;
        int b = vb2 >> 8;
        int chunk = vb2 & 255;
        int base = chunk * 1024;
        const float* f = feat + (size_t)b * CC * PP;
        const int* lb = labels + (size_t)b * PP;

        {
            int n = wid, c = lane;
            float cntv = g_counts[b][n];
            V->sm[n * 36 + c] = g_sums[b][n][c] / cntv;
            if (c == 0) V->sinv[n] = 1.0f / cntv;
        }
        __syncthreads();

        int p4 = base + t * 4;
        int4 L = *(const int4*)&lb[p4];
        int lv[4] = { L.x, L.y, L.z, L.w };

        float d2[4] = { 0.0f, 0.0f, 0.0f, 0.0f };
#pragma unroll
        for (int cg = 0; cg < 8; cg++) {
            float4 v0 = *(const float4*)&f[(size_t)(cg * 4 + 0) * PP + p4];
            float4 v1 = *(const float4*)&f[(size_t)(cg * 4 + 1) * PP + p4];
            float4 v2 = *(const float4*)&f[(size_t)(cg * 4 + 2) * PP + p4];
            float4 v3 = *(const float4*)&f[(size_t)(cg * 4 + 3) * PP + p4];
            float vj[4][4] = { {v0.x, v1.x, v2.x, v3.x},
                               {v0.y, v1.y, v2.y, v3.y},
                               {v0.z, v1.z, v2.z, v3.z},
                               {v0.w, v1.w, v2.w, v3.w} };
#pragma unroll
            for (int j = 0; j < 4; j++) {
                float4 m = *(const float4*)&V->sm[lv[j] * 36 + cg * 4];
                float t0 = vj[j][0] - m.x;
                float t1 = vj[j][1] - m.y;
                float t2 = vj[j][2] - m.z;
                float t3 = vj[j][3] - m.w;
                d2[j] += t0 * t0 + t1 * t1 + t2 * t2 + t3 * t3;
            }
        }

        float hsum = 0.0f;
#pragma unroll
        for (int j = 0; j < 4; j++) {
            float d = sqrtf(d2[j] + 1e-12f);
            float h = fmaxf(d - 0.5f, 0.0f);          // DV = 0.5
            hsum += h * h * V->sinv[lv[j]];
        }
#pragma unroll
        for (int o = 16; o > 0; o >>= 1) hsum += __shfl_xor_sync(0xffffffffu, hsum, o);
        if (lane == 0) V->wred[wid] = hsum;
        __syncthreads();
        if (t == 0) {
            float s = 0.0f;
#pragma unroll
            for (int w2 = 0; w2 < 8; w2++) s += V->wred[w2];
            g_var_part[vb2] = s;
        }
    } else {
        // --------------------------- pair loss (mma) --------------------------
        PairS* P = reinterpret_cast<PairS*>(Sbuf);
        int id = blockIdx.x - VAR_BLKS;
        int b = id / (NPAIRS * 8);
        int r2 = id % (NPAIRS * 8);
        int pair = r2 >> 3;
        int tile = r2 & 7;
        int i = 0, rem = pair;
        while (rem >= (NI - 1) - i) { rem -= (NI - 1) - i; i++; }
        int j = i + 1 + rem;
        int ti = tile >> 1, tj = tile & 1;
        int i0 = i * EE + ti * 128;
        int j0 = j * EE + tj * 256;

        {
            int row4 = t >> 2, ch8 = (t & 3) * 8;
#pragma unroll
            for (int rr = 0; rr < 2; rr++)
                *(uint4*)&P->As[row4 + rr * 64][ch8] =
                    *(const uint4*)&g_ebh[b][i0 + row4 + rr * 64][ch8];
#pragma unroll
            for (int rr = 0; rr < 4; rr++)
                *(uint4*)&P->Bs[row4 + rr * 64][ch8] =
                    *(const uint4*)&g_ebh[b][j0 + row4 + rr * 64][ch8];
        }
        if (t < 128) P->sqa[t] = g_sq[b][i0 + t];
        P->sqb[t] = g_sq[b][j0 + t];
        __syncthreads();

        int wi = wid >> 1, wj = wid & 1;
        int r0 = wi * 32, cb0 = wj * 128;
        int g = lane >> 2, tq = lane & 3;

        unsigned a[2][2][4];
#pragma unroll
        for (int rb = 0; rb < 2; rb++)
#pragma unroll
            for (int ks = 0; ks < 2; ks++) {
                int rbase = r0 + rb * 16;
                int kb = ks * 16 + 2 * tq;
                a[rb][ks][0] = *(const unsigned*)&P->As[rbase + g][kb];
                a[rb][ks][1] = *(const unsigned*)&P->As[rbase + g + 8][kb];
                a[rb][ks][2] = *(const unsigned*)&P->As[rbase + g][kb + 8];
                a[rb][ks][3] = *(const unsigned*)&P->As[rbase + g + 8][kb + 8];
            }
        float sa0[2] = { P->sqa[r0 + g],     P->sqa[r0 + 16 + g] };
        float sa1[2] = { P->sqa[r0 + 8 + g], P->sqa[r0 + 24 + g] };

        unsigned bs_u32 = (unsigned)__cvta_generic_to_shared(&P->Bs[0][0]);
        unsigned baddr = bs_u32 +
            (unsigned)(((cb0 + (lane & 7)) * 40 + (lane >> 3) * 8) * 2);

        float mn0 = 1e30f, mn1 = 1e30f, mn2 = 1e30f, mn3 = 1e30f;
#pragma unroll
        for (int nt = 0; nt < 16; nt++) {
            unsigned b00, b01, b10, b11;
            asm volatile(
                "ldmatrix.sync.aligned.m8n8.x4.shared.b16 {%0,%1,%2,%3}, [%4];"
                : "=r"(b00), "=r"(b01), "=r"(b10), "=r"(b11)
                : "r"(baddr + (unsigned)(nt * 8 * 80)));
            float2 sb = *(const float2*)&P->sqb[cb0 + nt * 8 + 2 * tq];
#pragma unroll
            for (int rb = 0; rb < 2; rb++) {
                float d0 = 0.0f, d1 = 0.0f, d2v = 0.0f, d3 = 0.0f;
                asm volatile(
                    "mma.sync.aligned.m16n8k16.row.col.f32.bf16.bf16.f32 "
                    "{%0,%1,%2,%3}, {%4,%5,%6,%7}, {%8,%9}, {%0,%1,%2,%3};"
                    : "+f"(d0), "+f"(d1), "+f"(d2v), "+f"(d3)
                    : "r"(a[rb][0][0]), "r"(a[rb][0][1]), "r"(a[rb][0][2]), "r"(a[rb][0][3]),
                      "r"(b00), "r"(b01));
                asm volatile(
                    "mma.sync.aligned.m16n8k16.row.col.f32.bf16.bf16.f32 "
                    "{%0,%1,%2,%3}, {%4,%5,%6,%7}, {%8,%9}, {%0,%1,%2,%3};"
                    : "+f"(d0), "+f"(d1), "+f"(d2v), "+f"(d3)
                    : "r"(a[rb][1][0]), "r"(a[rb][1][1]), "r"(a[rb][1][2]), "r"(a[rb][1][3]),
                      "r"(b10), "r"(b11));

                mn0 = fminf(mn0, fmaf(-2.0f, d0, sa0[rb] + sb.x));
                mn1 = fminf(mn1, fmaf(-2.0f, d1, sa0[rb] + sb.y));
                mn2 = fminf(mn2, fmaf(-2.0f, d2v, sa1[rb] + sb.x));
                mn3 = fminf(mn3, fmaf(-2.0f, d3, sa1[rb] + sb.y));
            }
        }
        float qmin = fminf(fminf(mn0, mn1), fminf(mn2, mn3));

        float acc = 0.0f;
        if (qmin < 4.0f) {
            // rare path: recompute with full hinge (deterministic MMAs)
#pragma unroll 1
            for (int nt = 0; nt < 16; nt++) {
                unsigned b00, b01, b10, b11;
                asm volatile(
                    "ldmatrix.sync.aligned.m8n8.x4.shared.b16 {%0,%1,%2,%3}, [%4];"
                    : "=r"(b00), "=r"(b01), "=r"(b10), "=r"(b11)
                    : "r"(baddr + (unsigned)(nt * 8 * 80)));
                float2 sb = *(const float2*)&P->sqb[cb0 + nt * 8 + 2 * tq];
#pragma unroll
                for (int rb = 0; rb < 2; rb++) {
                    float d0 = 0.0f, d1 = 0.0f, d2v = 0.0f, d3 = 0.0f;
                    asm volatile(
                        "mma.sync.aligned.m16n8k16.row.col.f32.bf16.bf16.f32 "
                        "{%0,%1,%2,%3}, {%4,%5,%6,%7}, {%8,%9}, {%0,%1,%2,%3};"
                        : "+f"(d0), "+f"(d1), "+f"(d2v), "+f"(d3)
                        : "r"(a[rb][0][0]), "r"(a[rb][0][1]), "r"(a[rb][0][2]), "r"(a[rb][0][3]),
                          "r"(b00), "r"(b01));
                    asm volatile(
                        "mma.sync.aligned.m16n8k16.row.col.f32.bf16.bf16.f32 "
                        "{%0,%1,%2,%3}, {%4,%5,%6,%7}, {%8,%9}, {%0,%1,%2,%3};"
                        : "+f"(d0), "+f"(d1), "+f"(d2v), "+f"(d3)
                        : "r"(a[rb][1][0]), "r"(a[rb][1][1]), "r"(a[rb][1][2]), "r"(a[rb][1][3]),
                          "r"(b10), "r"(b11));

                    float q00 = fmaf(-2.0f, d0, sa0[rb] + sb.x);
                    float q01 = fmaf(-2.0f, d1, sa0[rb] + sb.y);
                    float q10 = fmaf(-2.0f, d2v, sa1[rb] + sb.x);
                    float q11 = fmaf(-2.0f, d3, sa1[rb] + sb.y);
                    float h0 = fmaxf(2.0f - sqrtf(fmaxf(q00, 0.0f) + 1e-12f), 0.0f);
                    float h1 = fmaxf(2.0f - sqrtf(fmaxf(q01, 0.0f) + 1e-12f), 0.0f);
                    float h2 = fmaxf(2.0f - sqrtf(fmaxf(q10, 0.0f) + 1e-12f), 0.0f);
                    float h3 = fmaxf(2.0f - sqrtf(fmaxf(q11, 0.0f) + 1e-12f), 0.0f);
                    acc += h0 * h0 + h1 * h1 + h2 * h2 + h3 * h3;
                }
            }
        }

#pragma unroll
        for (int o = 16; o > 0; o >>= 1) acc += __shfl_xor_sync(0xffffffffu, acc, o);
        if (lane == 0) P->wred[wid] = acc;
        __syncthreads();
        if (t == 0) {
            float s = 0.0f;
#pragma unroll
            for (int w2 = 0; w2 < 8; w2++) s += P->wred[w2];
            g_edge_part[id] = s;
        }
    }

    // -------------------- ticket + last-block finalize ------------------------
    __threadfence();
    __syncthreads();
    if (t == 0) {
        int old = atomicAdd(&g_ticket, 1);
        s_last = (old == KVP_BLKS - 1);
    }
    __syncthreads();
    if (!s_last) return;

    FinS* F = reinterpret_cast<FinS*>(Sbuf);

    float vs = 0.0f, es = 0.0f;
#pragma unroll
    for (int k = 0; k < VAR_BLKS / 256; k++) vs += g_var_part[t + k * 256];
#pragma unroll
    for (int k = 0; k < 4; k++) {
        int idx = t + k * 256;
        if (idx < PAIR_BLKS) es += g_edge_part[idx];
    }
#pragma unroll
    for (int o = 16; o > 0; o >>= 1) {
        vs += __shfl_xor_sync(0xffffffffu, vs, o);
        es += __shfl_xor_sync(0xffffffffu, es, o);
    }
    if (lane == 0) { F->fv[wid] = vs; F->fe[wid] = es; }

    float dist_tot = 0.0f, reg_tot = 0.0f;
    for (int bb2 = 0; bb2 < BB; bb2++) {
        int n = wid, c = lane;
        float mean = g_sums[bb2][n][c] / g_counts[bb2][n];
        F->smm[n][c] = mean;
        if (t == 0) F->sdist = 0.0f;
        float m2 = mean * mean;
#pragma unroll
        for (int o = 16; o > 0; o >>= 1) m2 += __shfl_xor_sync(0xffffffffu, m2, o);
        if (lane == 0) F->sM2[n] = m2;
        __syncthreads();
        if (t < NPAIRS) {
            int ii = 0, rem2 = t;
            while (rem2 >= (NI - 1) - ii) { rem2 -= (NI - 1) - ii; ii++; }
            int jj = ii + 1 + rem2;
            float dd2 = 0.0f;
#pragma unroll
            for (int cc2 = 0; cc2 < CC; cc2++) {
                float df = F->smm[ii][cc2] - F->smm[jj][cc2];
                dd2 += df * df;
            }
            float dm = sqrtf(fmaxf(dd2, 0.0f) + 1e-12f);
            float h = fmaxf(3.0f - dm, 0.0f);   // 2*DD
            atomicAdd(&F->sdist, h * h);
        }
        __syncthreads();
        if (t == 0) {
            float r = 0.0f;
#pragma unroll
            for (int nn = 0; nn < NI; nn++)
                r += sqrtf(fmaxf(F->sM2[nn], 0.0f) + 1e-12f);
            reg_tot  += r * (1.0f / (float)NI);
            dist_tot += F->sdist;
        }
        __syncthreads();
    }

    // clear stats scratch + barriers for next replay
    {
        float* s4 = &g_sums[0][0][0];
        s4[t] = 0.0f; s4[t + 256] = 0.0f; s4[t + 512] = 0.0f; s4[t + 768] = 0.0f;
        if (t < BB * NI) (&g_counts[0][0])[t] = 0.0f;
    }

    if (t == 0) {
        float V = 0.0f, E = 0.0f;
#pragma unroll
        for (int w2 = 0; w2 < 8; w2++) { V += F->fv[w2]; E += F->fe[w2]; }
        float var  = V * (1.0f / (float)NI);
        float dist = dist_tot * (1.0f / 56.0f);
        float edge = E * (1.0f / (512.0f * 512.0f * 56.0f));
        float reg  = 0.001f * reg_tot;
        out[0] = var + dist + edge + reg;
        out[1] = var;
        out[2] = dist;
        out[3] = edge;
        out[4] = reg;
        g_ticket = 0;
        g_selbar = 0;
    }
}

// ------------------------------------------------------------------ launcher
extern "C" void kernel_launch(void* const* d_in, const int* in_sizes, int n_in,
                              void* d_out, int out_size) {
    const float* features   = (const float*)d_in[0];
    const int*   labels     = (const int*)d_in[1];
    const int*   labelEdges = (const int*)d_in[2];
    float* out = (float*)d_out;
    (void)in_sizes; (void)n_in; (void)out_size;

    kSelW<<<SEL_BLKS, 256>>>(labelEdges);
    kStats<<<STATS_BLKS, 512>>>(features, labels);
    kGath<<<GATH_BLKS, 256>>>(features);
    kVP<<<KVP_BLKS, 256>>>(features, labels, out);
}